// round 2
// baseline (speedup 1.0000x reference)
#include <cuda_runtime.h>
#include <math.h>

#define NB 4
#define SEQ 2048
#define DM 1024
#define DH 128

// Scratch (device globals: allocation-free rule)
__device__ float g_q[NB * SEQ * DH];
__device__ float g_k[NB * SEQ * DH];
__device__ float g_v[NB * SEQ * DH];
__device__ float g_ctx[NB * SEQ * DH];

__device__ __forceinline__ float grpmax16(float v) {
    v = fmaxf(v, __shfl_xor_sync(0xffffffffu, v, 1, 16));
    v = fmaxf(v, __shfl_xor_sync(0xffffffffu, v, 2, 16));
    v = fmaxf(v, __shfl_xor_sync(0xffffffffu, v, 4, 16));
    v = fmaxf(v, __shfl_xor_sync(0xffffffffu, v, 8, 16));
    return v;
}
__device__ __forceinline__ float grpsum16(float v) {
    v += __shfl_xor_sync(0xffffffffu, v, 1, 16);
    v += __shfl_xor_sync(0xffffffffu, v, 2, 16);
    v += __shfl_xor_sync(0xffffffffu, v, 4, 16);
    v += __shfl_xor_sync(0xffffffffu, v, 8, 16);
    return v;
}

// ---------------------------------------------------------------------------
// Kernel 1: QKV projection.  C[8192,128] = X[8192,1024] @ W[1024,128]
// grid = (128, 3); blockIdx.y selects (wq,wk,wv) -> (g_q,g_k,g_v)
// BM=64, BN=128(all), BK=32; 256 threads; 4x8 register tile per thread.
// ---------------------------------------------------------------------------
__global__ __launch_bounds__(256) void qkv_gemm(
    const float* __restrict__ x,
    const float* __restrict__ wq,
    const float* __restrict__ wk,
    const float* __restrict__ wv)
{
    __shared__ float Xs[32][68];    // [kk][row], pad 68 so float4 a-reads align
    __shared__ float Ws[32][128];   // [kk][col]

    const int tid = threadIdx.x;
    const int tr = tid >> 4;        // 0..15
    const int tc = tid & 15;        // 0..15
    const int m0 = blockIdx.x * 64;

    const float* w;
    float* o;
    if (blockIdx.y == 0)      { w = wq; o = g_q; }
    else if (blockIdx.y == 1) { w = wk; o = g_k; }
    else                      { w = wv; o = g_v; }

    float acc[4][8];
    #pragma unroll
    for (int i = 0; i < 4; i++)
        #pragma unroll
        for (int j = 0; j < 8; j++) acc[i][j] = 0.f;

    for (int k0 = 0; k0 < DM; k0 += 32) {
        // X tile 64x32 (transposed into Xs[kk][row]); coalesced gmem reads
        #pragma unroll
        for (int i = 0; i < 8; i++) {
            int idx = tid + i * 256;
            int r = idx >> 5, kk = idx & 31;
            Xs[kk][r] = x[(size_t)(m0 + r) * DM + k0 + kk];
        }
        // W tile 32x128, float4
        #pragma unroll
        for (int i = 0; i < 4; i++) {
            int idx = tid + i * 256;
            int kk = idx >> 5, c = (idx & 31) * 4;
            *(float4*)&Ws[kk][c] = *(const float4*)&w[(size_t)(k0 + kk) * DH + c];
        }
        __syncthreads();
        #pragma unroll
        for (int kk = 0; kk < 32; kk++) {
            float4 a  = *(float4*)&Xs[kk][tr * 4];
            float4 b0 = *(float4*)&Ws[kk][tc * 8];
            float4 b1 = *(float4*)&Ws[kk][tc * 8 + 4];
            float av[4] = {a.x, a.y, a.z, a.w};
            float bv[8] = {b0.x, b0.y, b0.z, b0.w, b1.x, b1.y, b1.z, b1.w};
            #pragma unroll
            for (int i = 0; i < 4; i++)
                #pragma unroll
                for (int j = 0; j < 8; j++)
                    acc[i][j] = fmaf(av[i], bv[j], acc[i][j]);
        }
        __syncthreads();
    }
    #pragma unroll
    for (int i = 0; i < 4; i++) {
        size_t row = (size_t)(m0 + tr * 4 + i);
        float4 v0 = make_float4(acc[i][0], acc[i][1], acc[i][2], acc[i][3]);
        float4 v1 = make_float4(acc[i][4], acc[i][5], acc[i][6], acc[i][7]);
        *(float4*)&o[row * DH + tc * 8]     = v0;
        *(float4*)&o[row * DH + tc * 8 + 4] = v1;
    }
}

// ---------------------------------------------------------------------------
// Kernel 2: causal flash attention.  BM=64 queries, BN=64 keys, H=128.
// grid = (SEQ/64, NB); 256 threads.
// Dynamic smem: Qs[64][128] | KV union (Kt[128][65] / V[64][128]) | Ps[64][65]
// ---------------------------------------------------------------------------
#define ATTN_SMEM_FLOATS (64 * 128 + 128 * 65 + 64 * 65)
#define ATTN_SMEM_BYTES  (ATTN_SMEM_FLOATS * 4)

__global__ __launch_bounds__(256) void attn_kernel()
{
    extern __shared__ float sm[];
    float* Qs = sm;                    // 64*128
    float* KV = sm + 64 * 128;         // Kt[128][65] then reused as V[64][128]
    float* Ps = KV + 128 * 65;         // 64*65

    const int tid = threadIdx.x;
    const int tr = tid >> 4;           // query sub-row group 0..15
    const int tc = tid & 15;           // key/col group 0..15
    const int b = blockIdx.y;
    const int q0 = blockIdx.x * 64;
    const float scale = 0.088388347648318447f;   // 1/sqrt(128)

    const float* qg = g_q + (size_t)b * SEQ * DH;
    const float* kg = g_k + (size_t)b * SEQ * DH;
    const float* vg = g_v + (size_t)b * SEQ * DH;

    // Load Q tile (pre-scaled)
    #pragma unroll
    for (int i = 0; i < 8; i++) {
        int idx = tid + i * 256;
        int r = idx >> 5, c = (idx & 31) * 4;
        float4 qv = *(const float4*)&qg[(size_t)(q0 + r) * DH + c];
        qv.x *= scale; qv.y *= scale; qv.z *= scale; qv.w *= scale;
        *(float4*)&Qs[r * DH + c] = qv;
    }

    float m_i[4], l_i[4], O[4][8];
    #pragma unroll
    for (int i = 0; i < 4; i++) { m_i[i] = -1e30f; l_i[i] = 0.f; }
    #pragma unroll
    for (int i = 0; i < 4; i++)
        #pragma unroll
        for (int j = 0; j < 8; j++) O[i][j] = 0.f;

    for (int k0 = 0; k0 <= q0; k0 += 64) {
        __syncthreads();   // protects Qs (iter 0) and KV-as-V reads (iter >0)
        // K tile transposed: Kt[h][kk], stride 65 -> conflict-free stores
        #pragma unroll
        for (int i = 0; i < 32; i++) {
            int idx = tid + i * 256;
            int kk = idx >> 7, h = idx & 127;
            KV[h * 65 + kk] = kg[(size_t)(k0 + kk) * DH + h];
        }
        __syncthreads();

        // S = Q @ K^T (4x4 per thread)
        float s[4][4];
        #pragma unroll
        for (int i = 0; i < 4; i++)
            #pragma unroll
            for (int j = 0; j < 4; j++) s[i][j] = 0.f;

        #pragma unroll 4
        for (int h = 0; h < DH; h++) {
            float a0 = Qs[(tr * 4 + 0) * DH + h];
            float a1 = Qs[(tr * 4 + 1) * DH + h];
            float a2 = Qs[(tr * 4 + 2) * DH + h];
            float a3 = Qs[(tr * 4 + 3) * DH + h];
            float b0 = KV[h * 65 + tc * 4 + 0];
            float b1 = KV[h * 65 + tc * 4 + 1];
            float b2 = KV[h * 65 + tc * 4 + 2];
            float b3 = KV[h * 65 + tc * 4 + 3];
            s[0][0] = fmaf(a0, b0, s[0][0]); s[0][1] = fmaf(a0, b1, s[0][1]);
            s[0][2] = fmaf(a0, b2, s[0][2]); s[0][3] = fmaf(a0, b3, s[0][3]);
            s[1][0] = fmaf(a1, b0, s[1][0]); s[1][1] = fmaf(a1, b1, s[1][1]);
            s[1][2] = fmaf(a1, b2, s[1][2]); s[1][3] = fmaf(a1, b3, s[1][3]);
            s[2][0] = fmaf(a2, b0, s[2][0]); s[2][1] = fmaf(a2, b1, s[2][1]);
            s[2][2] = fmaf(a2, b2, s[2][2]); s[2][3] = fmaf(a2, b3, s[2][3]);
            s[3][0] = fmaf(a3, b0, s[3][0]); s[3][1] = fmaf(a3, b1, s[3][1]);
            s[3][2] = fmaf(a3, b2, s[3][2]); s[3][3] = fmaf(a3, b3, s[3][3]);
        }

        // Causal mask only on the diagonal tile
        if (k0 == q0) {
            #pragma unroll
            for (int i = 0; i < 4; i++)
                #pragma unroll
                for (int j = 0; j < 4; j++)
                    if (tc * 4 + j > tr * 4 + i) s[i][j] = -1e30f;
        }

        // Online softmax update (rows split across 16-lane groups)
        #pragma unroll
        for (int i = 0; i < 4; i++) {
            float rmax = fmaxf(fmaxf(s[i][0], s[i][1]), fmaxf(s[i][2], s[i][3]));
            rmax = grpmax16(rmax);
            float mnew = fmaxf(m_i[i], rmax);
            float corr = __expf(m_i[i] - mnew);
            m_i[i] = mnew;
            l_i[i] *= corr;
            #pragma unroll
            for (int j = 0; j < 8; j++) O[i][j] *= corr;
            float ps = 0.f;
            #pragma unroll
            for (int j = 0; j < 4; j++) {
                float p = __expf(s[i][j] - mnew);
                s[i][j] = p;
                ps += p;
            }
            ps = grpsum16(ps);
            l_i[i] += ps;
            #pragma unroll
            for (int j = 0; j < 4; j++)
                Ps[(tr * 4 + i) * 65 + tc * 4 + j] = s[i][j];
        }
        __syncthreads();   // all Kt reads done; P in smem

        // V tile row-major into the same buffer (union with Kt)
        #pragma unroll
        for (int i = 0; i < 8; i++) {
            int idx = tid + i * 256;
            int kk = idx >> 5, c = (idx & 31) * 4;
            *(float4*)&KV[kk * DH + c] = *(const float4*)&vg[(size_t)(k0 + kk) * DH + c];
        }
        __syncthreads();

        // O += P @ V  (4x8 per thread)
        #pragma unroll 4
        for (int kk = 0; kk < 64; kk++) {
            float p0 = Ps[(tr * 4 + 0) * 65 + kk];
            float p1 = Ps[(tr * 4 + 1) * 65 + kk];
            float p2 = Ps[(tr * 4 + 2) * 65 + kk];
            float p3 = Ps[(tr * 4 + 3) * 65 + kk];
            float4 v0 = *(float4*)&KV[kk * DH + tc * 8];
            float4 v1 = *(float4*)&KV[kk * DH + tc * 8 + 4];
            float vv[8] = {v0.x, v0.y, v0.z, v0.w, v1.x, v1.y, v1.z, v1.w};
            #pragma unroll
            for (int j = 0; j < 8; j++) {
                O[0][j] = fmaf(p0, vv[j], O[0][j]);
                O[1][j] = fmaf(p1, vv[j], O[1][j]);
                O[2][j] = fmaf(p2, vv[j], O[2][j]);
                O[3][j] = fmaf(p3, vv[j], O[3][j]);
            }
        }
    }

    // Epilogue: normalize and write ctx
    float* cg = g_ctx + (size_t)b * SEQ * DH;
    #pragma unroll
    for (int i = 0; i < 4; i++) {
        float inv = 1.f / l_i[i];
        size_t row = (size_t)(q0 + tr * 4 + i);
        float4 v0 = make_float4(O[i][0] * inv, O[i][1] * inv, O[i][2] * inv, O[i][3] * inv);
        float4 v1 = make_float4(O[i][4] * inv, O[i][5] * inv, O[i][6] * inv, O[i][7] * inv);
        *(float4*)&cg[row * DH + tc * 8]     = v0;
        *(float4*)&cg[row * DH + tc * 8 + 4] = v1;
    }
}

// ---------------------------------------------------------------------------
// Kernel 3: output projection. out[8192,1024] = ctx[8192,128] @ wo[128,1024]
// grid = (128, 8); BM=64, BN=128, BK=32.
// ---------------------------------------------------------------------------
__global__ __launch_bounds__(256) void proj_gemm(
    const float* __restrict__ wo, float* __restrict__ out)
{
    __shared__ float Xs[32][68];
    __shared__ float Ws[32][128];

    const int tid = threadIdx.x;
    const int tr = tid >> 4, tc = tid & 15;
    const int m0 = blockIdx.x * 64;
    const int n0 = blockIdx.y * 128;

    float acc[4][8];
    #pragma unroll
    for (int i = 0; i < 4; i++)
        #pragma unroll
        for (int j = 0; j < 8; j++) acc[i][j] = 0.f;

    for (int k0 = 0; k0 < DH; k0 += 32) {
        #pragma unroll
        for (int i = 0; i < 8; i++) {
            int idx = tid + i * 256;
            int r = idx >> 5, kk = idx & 31;
            Xs[kk][r] = g_ctx[(size_t)(m0 + r) * DH + k0 + kk];
        }
        #pragma unroll
        for (int i = 0; i < 4; i++) {
            int idx = tid + i * 256;
            int kk = idx >> 5, c = (idx & 31) * 4;
            *(float4*)&Ws[kk][c] = *(const float4*)&wo[(size_t)(k0 + kk) * DM + n0 + c];
        }
        __syncthreads();
        #pragma unroll
        for (int kk = 0; kk < 32; kk++) {
            float4 a  = *(float4*)&Xs[kk][tr * 4];
            float4 b0 = *(float4*)&Ws[kk][tc * 8];
            float4 b1 = *(float4*)&Ws[kk][tc * 8 + 4];
            float av[4] = {a.x, a.y, a.z, a.w};
            float bv[8] = {b0.x, b0.y, b0.z, b0.w, b1.x, b1.y, b1.z, b1.w};
            #pragma unroll
            for (int i = 0; i < 4; i++)
                #pragma unroll
                for (int j = 0; j < 8; j++)
                    acc[i][j] = fmaf(av[i], bv[j], acc[i][j]);
        }
        __syncthreads();
    }
    #pragma unroll
    for (int i = 0; i < 4; i++) {
        size_t row = (size_t)(m0 + tr * 4 + i);
        float4 v0 = make_float4(acc[i][0], acc[i][1], acc[i][2], acc[i][3]);
        float4 v1 = make_float4(acc[i][4], acc[i][5], acc[i][6], acc[i][7]);
        *(float4*)&out[row * DM + n0 + tc * 8]     = v0;
        *(float4*)&out[row * DM + n0 + tc * 8 + 4] = v1;
    }
}

// ---------------------------------------------------------------------------
extern "C" void kernel_launch(void* const* d_in, const int* in_sizes, int n_in,
                              void* d_out, int out_size)
{
    const float* x  = (const float*)d_in[0];
    const float* wq = (const float*)d_in[1];
    const float* wk = (const float*)d_in[2];
    const float* wv = (const float*)d_in[3];
    const float* wo = (const float*)d_in[4];
    float* out = (float*)d_out;

    (void)in_sizes; (void)n_in; (void)out_size;

    // QKV projections
    qkv_gemm<<<dim3(NB * SEQ / 64, 3), 256>>>(x, wq, wk, wv);

    // Flash attention (needs >48KB dynamic smem)
    cudaFuncSetAttribute(attn_kernel,
                         cudaFuncAttributeMaxDynamicSharedMemorySize,
                         ATTN_SMEM_BYTES);
    attn_kernel<<<dim3(SEQ / 64, NB), 256, ATTN_SMEM_BYTES>>>();

    // Output projection
    proj_gemm<<<dim3(NB * SEQ / 64, DM / 128), 256>>>(wo, out);
}

// round 3
// speedup vs baseline: 2.9976x; 2.9976x over previous
#include <cuda_runtime.h>
#include <math.h>

#define NB 4
#define SEQ 2048
#define DM 1024
#define DH 128
typedef unsigned int U32;

// Scratch (device globals: allocation-free rule)
__device__ float g_q[NB * SEQ * DH];
__device__ float g_k[NB * SEQ * DH];
__device__ float g_v[NB * SEQ * DH];
__device__ float g_ctx[NB * SEQ * DH];

// ---------------------------------------------------------------------------
// tf32 helpers
// ---------------------------------------------------------------------------
__device__ __forceinline__ U32 f2tf(float f) {
    U32 u;
    asm("cvt.rna.tf32.f32 %0, %1;" : "=r"(u) : "f"(f));
    return u;
}

// D += A(16x8, row) * B(8x8, col) ; tf32 inputs, f32 accum
__device__ __forceinline__ void mma8(float* c, const U32* a, const U32* b) {
    asm volatile(
        "mma.sync.aligned.m16n8k8.row.col.f32.tf32.tf32.f32 "
        "{%0,%1,%2,%3}, {%4,%5,%6,%7}, {%8,%9}, {%0,%1,%2,%3};\n"
        : "+f"(c[0]), "+f"(c[1]), "+f"(c[2]), "+f"(c[3])
        : "r"(a[0]), "r"(a[1]), "r"(a[2]), "r"(a[3]),
          "r"(b[0]), "r"(b[1]));
}

// ---------------------------------------------------------------------------
// Kernel 1: QKV projection via tf32 tensor cores.
// C[8192,128] = X[8192,1024] @ W[1024,128]; grid=(128,3), 256 thr.
// CTA tile 64x128, BK=32. Warps 2x4, warp tile 32x32.
// Smem strides: Xs 36 (36%32=4 -> A frag conflict-free), Ws 136 (8 -> B frag cf)
// ---------------------------------------------------------------------------
__global__ __launch_bounds__(256) void qkv_tc(
    const float* __restrict__ x,
    const float* __restrict__ wq,
    const float* __restrict__ wk,
    const float* __restrict__ wv)
{
    __shared__ U32 Xs[64 * 36];
    __shared__ U32 Ws[32 * 136];

    const int tid = threadIdx.x;
    const int lane = tid & 31;
    const int wid = tid >> 5;
    const int wm = wid >> 2;     // 0..1
    const int wn = wid & 3;      // 0..3
    const int m0 = blockIdx.x * 64;
    const int lr = lane >> 2;    // 0..7
    const int lc = lane & 3;     // 0..3

    const float* w;
    float* o;
    if (blockIdx.y == 0)      { w = wq; o = g_q; }
    else if (blockIdx.y == 1) { w = wk; o = g_k; }
    else                      { w = wv; o = g_v; }

    float acc[2][4][4];
    #pragma unroll
    for (int mt = 0; mt < 2; mt++)
        #pragma unroll
        for (int nt = 0; nt < 4; nt++)
            #pragma unroll
            for (int j = 0; j < 4; j++) acc[mt][nt][j] = 0.f;

    for (int k0 = 0; k0 < DM; k0 += 32) {
        // X tile 64x32
        #pragma unroll
        for (int i = 0; i < 2; i++) {
            int idx = tid + i * 256;
            int r = idx >> 3, c4 = idx & 7;
            float4 v = *(const float4*)(x + (size_t)(m0 + r) * DM + k0 + c4 * 4);
            *(uint4*)&Xs[r * 36 + c4 * 4] =
                make_uint4(f2tf(v.x), f2tf(v.y), f2tf(v.z), f2tf(v.w));
        }
        // W tile 32x128
        #pragma unroll
        for (int i = 0; i < 4; i++) {
            int idx = tid + i * 256;
            int kk = idx >> 5, c4 = idx & 31;
            float4 v = *(const float4*)(w + (size_t)(k0 + kk) * DH + c4 * 4);
            *(uint4*)&Ws[kk * 136 + c4 * 4] =
                make_uint4(f2tf(v.x), f2tf(v.y), f2tf(v.z), f2tf(v.w));
        }
        __syncthreads();

        #pragma unroll
        for (int q8 = 0; q8 < 4; q8++) {
            int kb = q8 * 8;
            U32 a[2][4], b[4][2];
            #pragma unroll
            for (int mt = 0; mt < 2; mt++) {
                int r = wm * 32 + mt * 16 + lr;
                a[mt][0] = Xs[r * 36 + kb + lc];
                a[mt][1] = Xs[(r + 8) * 36 + kb + lc];
                a[mt][2] = Xs[r * 36 + kb + lc + 4];
                a[mt][3] = Xs[(r + 8) * 36 + kb + lc + 4];
            }
            #pragma unroll
            for (int nt = 0; nt < 4; nt++) {
                int n = wn * 32 + nt * 8 + lr;
                b[nt][0] = Ws[(kb + lc) * 136 + n];
                b[nt][1] = Ws[(kb + lc + 4) * 136 + n];
            }
            #pragma unroll
            for (int mt = 0; mt < 2; mt++)
                #pragma unroll
                for (int nt = 0; nt < 4; nt++)
                    mma8(acc[mt][nt], a[mt], b[nt]);
        }
        __syncthreads();
    }

    #pragma unroll
    for (int mt = 0; mt < 2; mt++)
        #pragma unroll
        for (int nt = 0; nt < 4; nt++) {
            int r = m0 + wm * 32 + mt * 16 + lr;
            int cc = wn * 32 + nt * 8 + 2 * lc;
            float2 v0 = make_float2(acc[mt][nt][0], acc[mt][nt][1]);
            float2 v1 = make_float2(acc[mt][nt][2], acc[mt][nt][3]);
            *(float2*)(o + (size_t)r * DH + cc) = v0;
            *(float2*)(o + (size_t)(r + 8) * DH + cc) = v1;
        }
}

// ---------------------------------------------------------------------------
// Kernel 2: causal flash attention on tensor cores.
// grid=(32,4), 128 thr (4 warps). BM=64 queries, BN=64 keys, head dim 128.
// Each warp owns 16 query rows end-to-end (full-row softmax, no cross-warp).
// Smem (dynamic, words): Qs[64*132] Ks[64*132] Vs[64*136] Ps[64*68] = 119808 B
// ---------------------------------------------------------------------------
#define ATTN_SMEM_WORDS (64 * 132 + 64 * 132 + 64 * 136 + 64 * 68)
#define ATTN_SMEM_BYTES (ATTN_SMEM_WORDS * 4)

__global__ __launch_bounds__(128) void attn_tc()
{
    extern __shared__ U32 sm[];
    U32* Qs = sm;                    // stride 132
    U32* Ks = sm + 64 * 132;         // stride 132
    U32* Vs = Ks + 64 * 132;         // stride 136
    U32* Ps = Vs + 64 * 136;         // stride 68

    const int tid = threadIdx.x;
    const int lane = tid & 31;
    const int wid = tid >> 5;        // 0..3, owns rows [wid*16, wid*16+16)
    const int lr = lane >> 2;
    const int lc = lane & 3;
    const int b = blockIdx.y;
    const int q0 = blockIdx.x * 64;
    const float scale = 0.088388347648318447f;  // 1/sqrt(128)

    const float* qg = g_q + (size_t)b * SEQ * DH;
    const float* kg = g_k + (size_t)b * SEQ * DH;
    const float* vg = g_v + (size_t)b * SEQ * DH;

    // Load Q tile (pre-scaled, tf32)
    #pragma unroll
    for (int i = 0; i < 16; i++) {
        int idx = tid + i * 128;
        int r = idx >> 5, c4 = idx & 31;
        float4 v = *(const float4*)(qg + (size_t)(q0 + r) * DH + c4 * 4);
        *(uint4*)&Qs[r * 132 + c4 * 4] = make_uint4(
            f2tf(v.x * scale), f2tf(v.y * scale),
            f2tf(v.z * scale), f2tf(v.w * scale));
    }

    float m0v = -1e30f, m1v = -1e30f, l0 = 0.f, l1 = 0.f;
    float O[16][4];
    #pragma unroll
    for (int nt = 0; nt < 16; nt++)
        #pragma unroll
        for (int j = 0; j < 4; j++) O[nt][j] = 0.f;

    const int rloc = wid * 16 + lr;

    for (int t = 0; t <= blockIdx.x; t++) {
        const int k0row = t * 64;
        __syncthreads();
        // K and V tiles (tf32 into smem)
        #pragma unroll
        for (int i = 0; i < 16; i++) {
            int idx = tid + i * 128;
            int r = idx >> 5, c4 = idx & 31;
            float4 kv = *(const float4*)(kg + (size_t)(k0row + r) * DH + c4 * 4);
            *(uint4*)&Ks[r * 132 + c4 * 4] =
                make_uint4(f2tf(kv.x), f2tf(kv.y), f2tf(kv.z), f2tf(kv.w));
            float4 vv = *(const float4*)(vg + (size_t)(k0row + r) * DH + c4 * 4);
            *(uint4*)&Vs[r * 136 + c4 * 4] =
                make_uint4(f2tf(vv.x), f2tf(vv.y), f2tf(vv.z), f2tf(vv.w));
        }
        __syncthreads();

        // S = Q @ K^T : warp computes rows [wid*16, +16) x all 64 keys
        float sc[8][4];
        #pragma unroll
        for (int nt = 0; nt < 8; nt++)
            #pragma unroll
            for (int j = 0; j < 4; j++) sc[nt][j] = 0.f;

        #pragma unroll
        for (int k8 = 0; k8 < 16; k8++) {
            int kb = k8 * 8;
            U32 a[4];
            a[0] = Qs[rloc * 132 + kb + lc];
            a[1] = Qs[(rloc + 8) * 132 + kb + lc];
            a[2] = Qs[rloc * 132 + kb + lc + 4];
            a[3] = Qs[(rloc + 8) * 132 + kb + lc + 4];
            #pragma unroll
            for (int nt = 0; nt < 8; nt++) {
                U32 bb[2];
                int n = nt * 8 + lr;
                bb[0] = Ks[n * 132 + kb + lc];
                bb[1] = Ks[n * 132 + kb + lc + 4];
                mma8(sc[nt], a, bb);
            }
        }

        // Causal mask on the diagonal tile (local row vs local col)
        if (t == blockIdx.x) {
            #pragma unroll
            for (int nt = 0; nt < 8; nt++) {
                int c0 = nt * 8 + 2 * lc;
                if (c0 > rloc)         sc[nt][0] = -1e30f;
                if (c0 + 1 > rloc)     sc[nt][1] = -1e30f;
                if (c0 > rloc + 8)     sc[nt][2] = -1e30f;
                if (c0 + 1 > rloc + 8) sc[nt][3] = -1e30f;
            }
        }

        // Online softmax (two rows per thread: rloc and rloc+8)
        float mx0 = -1e30f, mx1 = -1e30f;
        #pragma unroll
        for (int nt = 0; nt < 8; nt++) {
            mx0 = fmaxf(mx0, fmaxf(sc[nt][0], sc[nt][1]));
            mx1 = fmaxf(mx1, fmaxf(sc[nt][2], sc[nt][3]));
        }
        mx0 = fmaxf(mx0, __shfl_xor_sync(0xffffffffu, mx0, 1));
        mx0 = fmaxf(mx0, __shfl_xor_sync(0xffffffffu, mx0, 2));
        mx1 = fmaxf(mx1, __shfl_xor_sync(0xffffffffu, mx1, 1));
        mx1 = fmaxf(mx1, __shfl_xor_sync(0xffffffffu, mx1, 2));

        float mn0 = fmaxf(m0v, mx0), mn1 = fmaxf(m1v, mx1);
        float cr0 = __expf(m0v - mn0), cr1 = __expf(m1v - mn1);
        m0v = mn0; m1v = mn1;

        float s0 = 0.f, s1 = 0.f;
        #pragma unroll
        for (int nt = 0; nt < 8; nt++) {
            float p0 = __expf(sc[nt][0] - mn0);
            float p1 = __expf(sc[nt][1] - mn0);
            float p2 = __expf(sc[nt][2] - mn1);
            float p3 = __expf(sc[nt][3] - mn1);
            s0 += p0 + p1;
            s1 += p2 + p3;
            int c = nt * 8 + 2 * lc;
            *(uint2*)&Ps[rloc * 68 + c]       = make_uint2(f2tf(p0), f2tf(p1));
            *(uint2*)&Ps[(rloc + 8) * 68 + c] = make_uint2(f2tf(p2), f2tf(p3));
        }
        s0 += __shfl_xor_sync(0xffffffffu, s0, 1);
        s0 += __shfl_xor_sync(0xffffffffu, s0, 2);
        s1 += __shfl_xor_sync(0xffffffffu, s1, 1);
        s1 += __shfl_xor_sync(0xffffffffu, s1, 2);
        l0 = l0 * cr0 + s0;
        l1 = l1 * cr1 + s1;

        #pragma unroll
        for (int nt = 0; nt < 16; nt++) {
            O[nt][0] *= cr0; O[nt][1] *= cr0;
            O[nt][2] *= cr1; O[nt][3] *= cr1;
        }
        __syncwarp();

        // O += P @ V : k = 64 keys, n = 128 head dims
        #pragma unroll
        for (int k8 = 0; k8 < 8; k8++) {
            int kb = k8 * 8;
            U32 a[4];
            a[0] = Ps[rloc * 68 + kb + lc];
            a[1] = Ps[(rloc + 8) * 68 + kb + lc];
            a[2] = Ps[rloc * 68 + kb + lc + 4];
            a[3] = Ps[(rloc + 8) * 68 + kb + lc + 4];
            #pragma unroll
            for (int nt = 0; nt < 16; nt++) {
                U32 bb[2];
                int n = nt * 8 + lr;
                bb[0] = Vs[(kb + lc) * 136 + n];
                bb[1] = Vs[(kb + lc + 4) * 136 + n];
                mma8(O[nt], a, bb);
            }
        }
    }

    // Epilogue: normalize, write ctx
    float* cg = g_ctx + (size_t)b * SEQ * DH;
    float inv0 = 1.f / l0, inv1 = 1.f / l1;
    int rg = q0 + rloc;
    #pragma unroll
    for (int nt = 0; nt < 16; nt++) {
        int c = nt * 8 + 2 * lc;
        *(float2*)(cg + (size_t)rg * DH + c) =
            make_float2(O[nt][0] * inv0, O[nt][1] * inv0);
        *(float2*)(cg + (size_t)(rg + 8) * DH + c) =
            make_float2(O[nt][2] * inv1, O[nt][3] * inv1);
    }
}

// ---------------------------------------------------------------------------
// Kernel 3: output projection. out[8192,1024] = ctx[8192,128] @ wo[128,1024]
// grid=(128,8), 256 thr; CTA tile 64x128 (n0 = by*128), BK=32, K=128.
// ---------------------------------------------------------------------------
__global__ __launch_bounds__(256) void proj_tc(
    const float* __restrict__ wo, float* __restrict__ out)
{
    __shared__ U32 Xs[64 * 36];
    __shared__ U32 Ws[32 * 136];

    const int tid = threadIdx.x;
    const int lane = tid & 31;
    const int wid = tid >> 5;
    const int wm = wid >> 2;
    const int wn = wid & 3;
    const int m0 = blockIdx.x * 64;
    const int n0 = blockIdx.y * 128;
    const int lr = lane >> 2;
    const int lc = lane & 3;

    float acc[2][4][4];
    #pragma unroll
    for (int mt = 0; mt < 2; mt++)
        #pragma unroll
        for (int nt = 0; nt < 4; nt++)
            #pragma unroll
            for (int j = 0; j < 4; j++) acc[mt][nt][j] = 0.f;

    for (int k0 = 0; k0 < DH; k0 += 32) {
        #pragma unroll
        for (int i = 0; i < 2; i++) {
            int idx = tid + i * 256;
            int r = idx >> 3, c4 = idx & 7;
            float4 v = *(const float4*)(g_ctx + (size_t)(m0 + r) * DH + k0 + c4 * 4);
            *(uint4*)&Xs[r * 36 + c4 * 4] =
                make_uint4(f2tf(v.x), f2tf(v.y), f2tf(v.z), f2tf(v.w));
        }
        #pragma unroll
        for (int i = 0; i < 4; i++) {
            int idx = tid + i * 256;
            int kk = idx >> 5, c4 = idx & 31;
            float4 v = *(const float4*)(wo + (size_t)(k0 + kk) * DM + n0 + c4 * 4);
            *(uint4*)&Ws[kk * 136 + c4 * 4] =
                make_uint4(f2tf(v.x), f2tf(v.y), f2tf(v.z), f2tf(v.w));
        }
        __syncthreads();

        #pragma unroll
        for (int q8 = 0; q8 < 4; q8++) {
            int kb = q8 * 8;
            U32 a[2][4], b[4][2];
            #pragma unroll
            for (int mt = 0; mt < 2; mt++) {
                int r = wm * 32 + mt * 16 + lr;
                a[mt][0] = Xs[r * 36 + kb + lc];
                a[mt][1] = Xs[(r + 8) * 36 + kb + lc];
                a[mt][2] = Xs[r * 36 + kb + lc + 4];
                a[mt][3] = Xs[(r + 8) * 36 + kb + lc + 4];
            }
            #pragma unroll
            for (int nt = 0; nt < 4; nt++) {
                int n = wn * 32 + nt * 8 + lr;
                b[nt][0] = Ws[(kb + lc) * 136 + n];
                b[nt][1] = Ws[(kb + lc + 4) * 136 + n];
            }
            #pragma unroll
            for (int mt = 0; mt < 2; mt++)
                #pragma unroll
                for (int nt = 0; nt < 4; nt++)
                    mma8(acc[mt][nt], a[mt], b[nt]);
        }
        __syncthreads();
    }

    #pragma unroll
    for (int mt = 0; mt < 2; mt++)
        #pragma unroll
        for (int nt = 0; nt < 4; nt++) {
            int r = m0 + wm * 32 + mt * 16 + lr;
            int cc = n0 + wn * 32 + nt * 8 + 2 * lc;
            *(float2*)(out + (size_t)r * DM + cc) =
                make_float2(acc[mt][nt][0], acc[mt][nt][1]);
            *(float2*)(out + (size_t)(r + 8) * DM + cc) =
                make_float2(acc[mt][nt][2], acc[mt][nt][3]);
        }
}

// ---------------------------------------------------------------------------
extern "C" void kernel_launch(void* const* d_in, const int* in_sizes, int n_in,
                              void* d_out, int out_size)
{
    const float* x  = (const float*)d_in[0];
    const float* wq = (const float*)d_in[1];
    const float* wk = (const float*)d_in[2];
    const float* wv = (const float*)d_in[3];
    const float* wo = (const float*)d_in[4];
    float* out = (float*)d_out;
    (void)in_sizes; (void)n_in; (void)out_size;

    qkv_tc<<<dim3(NB * SEQ / 64, 3), 256>>>(x, wq, wk, wv);

    cudaFuncSetAttribute(attn_tc,
                         cudaFuncAttributeMaxDynamicSharedMemorySize,
                         ATTN_SMEM_BYTES);
    attn_tc<<<dim3(SEQ / 64, NB), 128, ATTN_SMEM_BYTES>>>();

    proj_tc<<<dim3(NB * SEQ / 64, DM / 128), 256>>>(wo, out);
}

// round 4
// speedup vs baseline: 5.3497x; 1.7846x over previous
#include <cuda_runtime.h>
#include <math.h>

#define NB 4
#define SEQ 2048
#define DM 1024
#define DH 128
#define CHUNK 8                 // kv tiles (of 64) per attention CTA
#define NQT (SEQ / 64)          // 32 q-tiles
#define CPB 80                  // chunks per batch = 8*(1+2+3+4)
typedef unsigned int U32;

// Scratch (device globals: allocation-free rule)
__device__ float g_q[NB * SEQ * DH];
__device__ float g_k[NB * SEQ * DH];
__device__ float g_v[NB * SEQ * DH];
__device__ float g_ctx[NB * SEQ * DH];
// split-KV partials: [b][qt][kc][64 rows][128] + per-row m,l
__device__ float g_pO[NB * NQT * 4 * 64 * DH];
__device__ float g_pm[NB * NQT * 4 * 64];
__device__ float g_pl[NB * NQT * 4 * 64];

// ---------------------------------------------------------------------------
__device__ __forceinline__ U32 f2tf(float f) {
    U32 u;
    asm("cvt.rna.tf32.f32 %0, %1;" : "=r"(u) : "f"(f));
    return u;
}
__device__ __forceinline__ void mma8(float* c, const U32* a, const U32* b) {
    asm volatile(
        "mma.sync.aligned.m16n8k8.row.col.f32.tf32.tf32.f32 "
        "{%0,%1,%2,%3}, {%4,%5,%6,%7}, {%8,%9}, {%0,%1,%2,%3};\n"
        : "+f"(c[0]), "+f"(c[1]), "+f"(c[2]), "+f"(c[3])
        : "r"(a[0]), "r"(a[1]), "r"(a[2]), "r"(a[3]),
          "r"(b[0]), "r"(b[1]));
}

// ---------------------------------------------------------------------------
// Kernel 1: QKV projection, tf32 TC, register-prefetch double buffering.
// grid=(128,3), 256 thr; CTA 64x128, BK=32; warps 2x4 (warp tile 32x32).
// ---------------------------------------------------------------------------
__global__ __launch_bounds__(256) void qkv_tc(
    const float* __restrict__ x,
    const float* __restrict__ wq,
    const float* __restrict__ wk,
    const float* __restrict__ wv)
{
    __shared__ U32 Xs[64 * 36];
    __shared__ U32 Ws[32 * 136];

    const int tid = threadIdx.x;
    const int lane = tid & 31;
    const int wid = tid >> 5;
    const int wm = wid >> 2;
    const int wn = wid & 3;
    const int m0 = blockIdx.x * 64;
    const int lr = lane >> 2;
    const int lc = lane & 3;

    const float* w;
    float* o;
    if (blockIdx.y == 0)      { w = wq; o = g_q; }
    else if (blockIdx.y == 1) { w = wk; o = g_k; }
    else                      { w = wv; o = g_v; }

    // per-thread staging registers for the prefetch pipeline
    const int xr_r  = tid >> 3,  xr_c = (tid & 7) * 4;        // X: 64x32, 2 f4/thr
    const int wr_k  = tid >> 5,  wr_c = (tid & 31) * 4;       // W: 32x128, 4 f4/thr
    float4 xr[2], wr[4];

    #pragma unroll
    for (int i = 0; i < 2; i++)
        xr[i] = *(const float4*)(x + (size_t)(m0 + xr_r + i * 32) * DM + xr_c);
    #pragma unroll
    for (int i = 0; i < 4; i++)
        wr[i] = *(const float4*)(w + (size_t)(wr_k + i * 8) * DH + wr_c);

    float acc[2][4][4];
    #pragma unroll
    for (int mt = 0; mt < 2; mt++)
        #pragma unroll
        for (int nt = 0; nt < 4; nt++)
            #pragma unroll
            for (int j = 0; j < 4; j++) acc[mt][nt][j] = 0.f;

    for (int k0 = 0; k0 < DM; k0 += 32) {
        // commit staged tile to smem (tf32)
        #pragma unroll
        for (int i = 0; i < 2; i++)
            *(uint4*)&Xs[(xr_r + i * 32) * 36 + xr_c] =
                make_uint4(f2tf(xr[i].x), f2tf(xr[i].y), f2tf(xr[i].z), f2tf(xr[i].w));
        #pragma unroll
        for (int i = 0; i < 4; i++)
            *(uint4*)&Ws[(wr_k + i * 8) * 136 + wr_c] =
                make_uint4(f2tf(wr[i].x), f2tf(wr[i].y), f2tf(wr[i].z), f2tf(wr[i].w));
        __syncthreads();

        // prefetch next tile while MMAs run
        if (k0 + 32 < DM) {
            #pragma unroll
            for (int i = 0; i < 2; i++)
                xr[i] = *(const float4*)(x + (size_t)(m0 + xr_r + i * 32) * DM + k0 + 32 + xr_c);
            #pragma unroll
            for (int i = 0; i < 4; i++)
                wr[i] = *(const float4*)(w + (size_t)(k0 + 32 + wr_k + i * 8) * DH + wr_c);
        }

        #pragma unroll
        for (int q8 = 0; q8 < 4; q8++) {
            int kb = q8 * 8;
            U32 a[2][4], b[4][2];
            #pragma unroll
            for (int mt = 0; mt < 2; mt++) {
                int r = wm * 32 + mt * 16 + lr;
                a[mt][0] = Xs[r * 36 + kb + lc];
                a[mt][1] = Xs[(r + 8) * 36 + kb + lc];
                a[mt][2] = Xs[r * 36 + kb + lc + 4];
                a[mt][3] = Xs[(r + 8) * 36 + kb + lc + 4];
            }
            #pragma unroll
            for (int nt = 0; nt < 4; nt++) {
                int n = wn * 32 + nt * 8 + lr;
                b[nt][0] = Ws[(kb + lc) * 136 + n];
                b[nt][1] = Ws[(kb + lc + 4) * 136 + n];
            }
            #pragma unroll
            for (int mt = 0; mt < 2; mt++)
                #pragma unroll
                for (int nt = 0; nt < 4; nt++)
                    mma8(acc[mt][nt], a[mt], b[nt]);
        }
        __syncthreads();
    }

    #pragma unroll
    for (int mt = 0; mt < 2; mt++)
        #pragma unroll
        for (int nt = 0; nt < 4; nt++) {
            int r = m0 + wm * 32 + mt * 16 + lr;
            int cc = wn * 32 + nt * 8 + 2 * lc;
            *(float2*)(o + (size_t)r * DH + cc) =
                make_float2(acc[mt][nt][0], acc[mt][nt][1]);
            *(float2*)(o + (size_t)(r + 8) * DH + cc) =
                make_float2(acc[mt][nt][2], acc[mt][nt][3]);
        }
}

// ---------------------------------------------------------------------------
// Kernel 2: split-KV causal flash attention (tf32 TC).
// grid=(80,4), 128 thr (4 warps; each warp owns 16 query rows).
// Chunk = up to 8 kv-tiles of 64 keys. Partials (m,l,O) -> g_p*.
// Smem: Qs[64*132] | KV union[64*136] (K stride 132 / V stride 136) | Ps[64*68]
// = 86016 B -> 2 CTAs/SM.
// ---------------------------------------------------------------------------
#define ATTN_SMEM_WORDS (64 * 132 + 64 * 136 + 64 * 68)
#define ATTN_SMEM_BYTES (ATTN_SMEM_WORDS * 4)

__global__ __launch_bounds__(128) void attn_tc()
{
    extern __shared__ U32 sm[];
    U32* Qs = sm;                    // stride 132
    U32* KV = sm + 64 * 132;         // union: K stride 132 / V stride 136
    U32* Ps = KV + 64 * 136;         // stride 68

    const int tid = threadIdx.x;
    const int lane = tid & 31;
    const int wid = tid >> 5;
    const int lr = lane >> 2;
    const int lc = lane & 3;
    const int b = blockIdx.y;
    const float scale = 0.088388347648318447f;   // 1/sqrt(128)

    // map blockIdx.x -> (q-tile, kv-chunk)
    int c = blockIdx.x, qt = 0, start = 0;
    for (;;) {
        int n = qt / 8 + 1;          // ceil((qt+1)/CHUNK)
        if (c < start + n) break;
        start += n;
        qt++;
    }
    const int kc = c - start;
    const int kt0 = kc * CHUNK;
    const int kt1 = min(kt0 + CHUNK, qt + 1);
    const int q0 = qt * 64;

    const float* qg = g_q + (size_t)b * SEQ * DH;
    const float* kg = g_k + (size_t)b * SEQ * DH;
    const float* vg = g_v + (size_t)b * SEQ * DH;

    // Q tile (pre-scaled tf32)
    #pragma unroll
    for (int i = 0; i < 16; i++) {
        int idx = tid + i * 128;
        int r = idx >> 5, c4 = idx & 31;
        float4 v = *(const float4*)(qg + (size_t)(q0 + r) * DH + c4 * 4);
        *(uint4*)&Qs[r * 132 + c4 * 4] = make_uint4(
            f2tf(v.x * scale), f2tf(v.y * scale),
            f2tf(v.z * scale), f2tf(v.w * scale));
    }

    float m0v = -1e30f, m1v = -1e30f, l0 = 0.f, l1 = 0.f;
    float O[16][4];
    #pragma unroll
    for (int nt = 0; nt < 16; nt++)
        #pragma unroll
        for (int j = 0; j < 4; j++) O[nt][j] = 0.f;

    const int rloc = wid * 16 + lr;

    for (int t = kt0; t < kt1; t++) {
        const int k0row = t * 64;
        __syncthreads();                          // prev PV reads of KV done (+Q ready)
        // K tile, stride 132
        #pragma unroll
        for (int i = 0; i < 16; i++) {
            int idx = tid + i * 128;
            int r = idx >> 5, c4 = idx & 31;
            float4 kv = *(const float4*)(kg + (size_t)(k0row + r) * DH + c4 * 4);
            *(uint4*)&KV[r * 132 + c4 * 4] =
                make_uint4(f2tf(kv.x), f2tf(kv.y), f2tf(kv.z), f2tf(kv.w));
        }
        __syncthreads();

        // S = Q @ K^T
        float sc[8][4];
        #pragma unroll
        for (int nt = 0; nt < 8; nt++)
            #pragma unroll
            for (int j = 0; j < 4; j++) sc[nt][j] = 0.f;

        #pragma unroll
        for (int k8 = 0; k8 < 16; k8++) {
            int kb = k8 * 8;
            U32 a[4];
            a[0] = Qs[rloc * 132 + kb + lc];
            a[1] = Qs[(rloc + 8) * 132 + kb + lc];
            a[2] = Qs[rloc * 132 + kb + lc + 4];
            a[3] = Qs[(rloc + 8) * 132 + kb + lc + 4];
            #pragma unroll
            for (int nt = 0; nt < 8; nt++) {
                U32 bb[2];
                int n = nt * 8 + lr;
                bb[0] = KV[n * 132 + kb + lc];
                bb[1] = KV[n * 132 + kb + lc + 4];
                mma8(sc[nt], a, bb);
            }
        }

        if (t == qt) {                             // diagonal tile: causal mask
            #pragma unroll
            for (int nt = 0; nt < 8; nt++) {
                int c0 = nt * 8 + 2 * lc;
                if (c0 > rloc)         sc[nt][0] = -1e30f;
                if (c0 + 1 > rloc)     sc[nt][1] = -1e30f;
                if (c0 > rloc + 8)     sc[nt][2] = -1e30f;
                if (c0 + 1 > rloc + 8) sc[nt][3] = -1e30f;
            }
        }

        // online softmax (rows rloc, rloc+8)
        float mx0 = -1e30f, mx1 = -1e30f;
        #pragma unroll
        for (int nt = 0; nt < 8; nt++) {
            mx0 = fmaxf(mx0, fmaxf(sc[nt][0], sc[nt][1]));
            mx1 = fmaxf(mx1, fmaxf(sc[nt][2], sc[nt][3]));
        }
        mx0 = fmaxf(mx0, __shfl_xor_sync(0xffffffffu, mx0, 1));
        mx0 = fmaxf(mx0, __shfl_xor_sync(0xffffffffu, mx0, 2));
        mx1 = fmaxf(mx1, __shfl_xor_sync(0xffffffffu, mx1, 1));
        mx1 = fmaxf(mx1, __shfl_xor_sync(0xffffffffu, mx1, 2));

        float mn0 = fmaxf(m0v, mx0), mn1 = fmaxf(m1v, mx1);
        float cr0 = __expf(m0v - mn0), cr1 = __expf(m1v - mn1);
        m0v = mn0; m1v = mn1;

        float s0 = 0.f, s1 = 0.f;
        #pragma unroll
        for (int nt = 0; nt < 8; nt++) {
            float p0 = __expf(sc[nt][0] - mn0);
            float p1 = __expf(sc[nt][1] - mn0);
            float p2 = __expf(sc[nt][2] - mn1);
            float p3 = __expf(sc[nt][3] - mn1);
            s0 += p0 + p1;
            s1 += p2 + p3;
            int cc = nt * 8 + 2 * lc;
            *(uint2*)&Ps[rloc * 68 + cc]       = make_uint2(f2tf(p0), f2tf(p1));
            *(uint2*)&Ps[(rloc + 8) * 68 + cc] = make_uint2(f2tf(p2), f2tf(p3));
        }
        s0 += __shfl_xor_sync(0xffffffffu, s0, 1);
        s0 += __shfl_xor_sync(0xffffffffu, s0, 2);
        s1 += __shfl_xor_sync(0xffffffffu, s1, 1);
        s1 += __shfl_xor_sync(0xffffffffu, s1, 2);
        l0 = l0 * cr0 + s0;
        l1 = l1 * cr1 + s1;

        #pragma unroll
        for (int nt = 0; nt < 16; nt++) {
            O[nt][0] *= cr0; O[nt][1] *= cr0;
            O[nt][2] *= cr1; O[nt][3] *= cr1;
        }

        __syncthreads();                          // K reads + Ps writes complete
        // V tile, stride 136 (same buffer)
        #pragma unroll
        for (int i = 0; i < 16; i++) {
            int idx = tid + i * 128;
            int r = idx >> 5, c4 = idx & 31;
            float4 vv = *(const float4*)(vg + (size_t)(k0row + r) * DH + c4 * 4);
            *(uint4*)&KV[r * 136 + c4 * 4] =
                make_uint4(f2tf(vv.x), f2tf(vv.y), f2tf(vv.z), f2tf(vv.w));
        }
        __syncthreads();

        // O += P @ V
        #pragma unroll
        for (int k8 = 0; k8 < 8; k8++) {
            int kb = k8 * 8;
            U32 a[4];
            a[0] = Ps[rloc * 68 + kb + lc];
            a[1] = Ps[(rloc + 8) * 68 + kb + lc];
            a[2] = Ps[rloc * 68 + kb + lc + 4];
            a[3] = Ps[(rloc + 8) * 68 + kb + lc + 4];
            #pragma unroll
            for (int nt = 0; nt < 16; nt++) {
                U32 bb[2];
                int n = nt * 8 + lr;
                bb[0] = KV[(kb + lc) * 136 + n];
                bb[1] = KV[(kb + lc + 4) * 136 + n];
                mma8(O[nt], a, bb);
            }
        }
    }

    // write partials (unnormalized O, plus m, l)
    const size_t pbase = (size_t)((b * NQT + qt) * 4 + kc);
    float* pO = g_pO + pbase * 64 * DH;
    #pragma unroll
    for (int nt = 0; nt < 16; nt++) {
        int cc = nt * 8 + 2 * lc;
        *(float2*)&pO[rloc * DH + cc]       = make_float2(O[nt][0], O[nt][1]);
        *(float2*)&pO[(rloc + 8) * DH + cc] = make_float2(O[nt][2], O[nt][3]);
    }
    if (lc == 0) {
        g_pm[pbase * 64 + rloc]     = m0v;
        g_pl[pbase * 64 + rloc]     = l0;
        g_pm[pbase * 64 + rloc + 8] = m1v;
        g_pl[pbase * 64 + rloc + 8] = l1;
    }
}

// ---------------------------------------------------------------------------
// Kernel 2b: combine split-KV partials -> g_ctx.
// grid=(32,4), 256 thr: 4 threads per query row (32 cols each).
// ---------------------------------------------------------------------------
__global__ __launch_bounds__(256) void attn_combine()
{
    const int qt = blockIdx.x, b = blockIdx.y;
    const int nc = qt / 8 + 1;
    const int row = threadIdx.x >> 2;
    const int cs = (threadIdx.x & 3) * 32;
    const size_t pb = (size_t)(b * NQT + qt) * 4;

    float m[4], l[4], w[4];
    float M = -1e30f;
    #pragma unroll 4
    for (int i = 0; i < nc; i++) {
        m[i] = g_pm[(pb + i) * 64 + row];
        l[i] = g_pl[(pb + i) * 64 + row];
        M = fmaxf(M, m[i]);
    }
    float L = 0.f;
    #pragma unroll 4
    for (int i = 0; i < nc; i++) {
        w[i] = __expf(m[i] - M);
        L += w[i] * l[i];
    }
    const float inv = 1.f / L;

    float acc[32];
    #pragma unroll
    for (int j = 0; j < 32; j++) acc[j] = 0.f;

    #pragma unroll 4
    for (int i = 0; i < nc; i++) {
        const float* p = g_pO + (pb + i) * 64 * DH + (size_t)row * DH + cs;
        float wi = w[i];
        #pragma unroll
        for (int j = 0; j < 8; j++) {
            float4 v = *(const float4*)(p + j * 4);
            acc[j * 4 + 0] += wi * v.x;
            acc[j * 4 + 1] += wi * v.y;
            acc[j * 4 + 2] += wi * v.z;
            acc[j * 4 + 3] += wi * v.w;
        }
    }

    float* cg = g_ctx + ((size_t)b * SEQ + qt * 64 + row) * DH + cs;
    #pragma unroll
    for (int j = 0; j < 8; j++)
        *(float4*)(cg + j * 4) = make_float4(acc[j * 4] * inv, acc[j * 4 + 1] * inv,
                                             acc[j * 4 + 2] * inv, acc[j * 4 + 3] * inv);
}

// ---------------------------------------------------------------------------
// Kernel 3: output projection with register prefetch.
// grid=(128,8), 256 thr; CTA 64x128, BK=32, K=128.
// ---------------------------------------------------------------------------
__global__ __launch_bounds__(256) void proj_tc(
    const float* __restrict__ wo, float* __restrict__ out)
{
    __shared__ U32 Xs[64 * 36];
    __shared__ U32 Ws[32 * 136];

    const int tid = threadIdx.x;
    const int lane = tid & 31;
    const int wid = tid >> 5;
    const int wm = wid >> 2;
    const int wn = wid & 3;
    const int m0 = blockIdx.x * 64;
    const int n0 = blockIdx.y * 128;
    const int lr = lane >> 2;
    const int lc = lane & 3;

    const int xr_r = tid >> 3,  xr_c = (tid & 7) * 4;
    const int wr_k = tid >> 5,  wr_c = (tid & 31) * 4;
    float4 xr[2], wr[4];

    #pragma unroll
    for (int i = 0; i < 2; i++)
        xr[i] = *(const float4*)(g_ctx + (size_t)(m0 + xr_r + i * 32) * DH + xr_c);
    #pragma unroll
    for (int i = 0; i < 4; i++)
        wr[i] = *(const float4*)(wo + (size_t)(wr_k + i * 8) * DM + n0 + wr_c);

    float acc[2][4][4];
    #pragma unroll
    for (int mt = 0; mt < 2; mt++)
        #pragma unroll
        for (int nt = 0; nt < 4; nt++)
            #pragma unroll
            for (int j = 0; j < 4; j++) acc[mt][nt][j] = 0.f;

    for (int k0 = 0; k0 < DH; k0 += 32) {
        #pragma unroll
        for (int i = 0; i < 2; i++)
            *(uint4*)&Xs[(xr_r + i * 32) * 36 + xr_c] =
                make_uint4(f2tf(xr[i].x), f2tf(xr[i].y), f2tf(xr[i].z), f2tf(xr[i].w));
        #pragma unroll
        for (int i = 0; i < 4; i++)
            *(uint4*)&Ws[(wr_k + i * 8) * 136 + wr_c] =
                make_uint4(f2tf(wr[i].x), f2tf(wr[i].y), f2tf(wr[i].z), f2tf(wr[i].w));
        __syncthreads();

        if (k0 + 32 < DH) {
            #pragma unroll
            for (int i = 0; i < 2; i++)
                xr[i] = *(const float4*)(g_ctx + (size_t)(m0 + xr_r + i * 32) * DH + k0 + 32 + xr_c);
            #pragma unroll
            for (int i = 0; i < 4; i++)
                wr[i] = *(const float4*)(wo + (size_t)(k0 + 32 + wr_k + i * 8) * DM + n0 + wr_c);
        }

        #pragma unroll
        for (int q8 = 0; q8 < 4; q8++) {
            int kb = q8 * 8;
            U32 a[2][4], b[4][2];
            #pragma unroll
            for (int mt = 0; mt < 2; mt++) {
                int r = wm * 32 + mt * 16 + lr;
                a[mt][0] = Xs[r * 36 + kb + lc];
                a[mt][1] = Xs[(r + 8) * 36 + kb + lc];
                a[mt][2] = Xs[r * 36 + kb + lc + 4];
                a[mt][3] = Xs[(r + 8) * 36 + kb + lc + 4];
            }
            #pragma unroll
            for (int nt = 0; nt < 4; nt++) {
                int n = wn * 32 + nt * 8 + lr;
                b[nt][0] = Ws[(kb + lc) * 136 + n];
                b[nt][1] = Ws[(kb + lc + 4) * 136 + n];
            }
            #pragma unroll
            for (int mt = 0; mt < 2; mt++)
                #pragma unroll
                for (int nt = 0; nt < 4; nt++)
                    mma8(acc[mt][nt], a[mt], b[nt]);
        }
        __syncthreads();
    }

    #pragma unroll
    for (int mt = 0; mt < 2; mt++)
        #pragma unroll
        for (int nt = 0; nt < 4; nt++) {
            int r = m0 + wm * 32 + mt * 16 + lr;
            int cc = n0 + wn * 32 + nt * 8 + 2 * lc;
            *(float2*)(out + (size_t)r * DM + cc) =
                make_float2(acc[mt][nt][0], acc[mt][nt][1]);
            *(float2*)(out + (size_t)(r + 8) * DM + cc) =
                make_float2(acc[mt][nt][2], acc[mt][nt][3]);
        }
}

// ---------------------------------------------------------------------------
extern "C" void kernel_launch(void* const* d_in, const int* in_sizes, int n_in,
                              void* d_out, int out_size)
{
    const float* x  = (const float*)d_in[0];
    const float* wq = (const float*)d_in[1];
    const float* wk = (const float*)d_in[2];
    const float* wv = (const float*)d_in[3];
    const float* wo = (const float*)d_in[4];
    float* out = (float*)d_out;
    (void)in_sizes; (void)n_in; (void)out_size;

    qkv_tc<<<dim3(NB * SEQ / 64, 3), 256>>>(x, wq, wk, wv);

    cudaFuncSetAttribute(attn_tc,
                         cudaFuncAttributeMaxDynamicSharedMemorySize,
                         ATTN_SMEM_BYTES);
    attn_tc<<<dim3(CPB, NB), 128, ATTN_SMEM_BYTES>>>();

    attn_combine<<<dim3(NQT, NB), 256>>>();

    proj_tc<<<dim3(NB * SEQ / 64, DM / 128), 256>>>(wo, out);
}